// round 9
// baseline (speedup 1.0000x reference)
#include <cuda_runtime.h>
#include <cstdint>

#define EMBED   1024
#define HEADS   16
#define HDIM    64
#define BATCH   2
#define SEQ     2048
#define MROWS   (BATCH*SEQ)          // 4096
#define OUT_ELEMS (MROWS*EMBED)      // 4194304

// ---------------- scratch (device globals: no allocation allowed) ----------
__device__ float g_Q[MROWS*EMBED];
__device__ float g_K[MROWS*EMBED];
__device__ float g_V[MROWS*EMBED];
__device__ float g_C[MROWS*EMBED];

// ---------------- helpers ---------------------------------------------------
__device__ __forceinline__ uint32_t f2tf(float f) {
    uint32_t u; asm("cvt.rna.tf32.f32 %0, %1;" : "=r"(u) : "f"(f)); return u;
}
__device__ __forceinline__ float tf2f(float f) { return __uint_as_float(f2tf(f)); }

__device__ __forceinline__ void mma8(float& c0, float& c1, float& c2, float& c3,
                                     uint32_t a0, uint32_t a1, uint32_t a2, uint32_t a3,
                                     uint32_t b0, uint32_t b1)
{
    asm volatile("mma.sync.aligned.m16n8k8.row.col.f32.tf32.tf32.f32 "
                 "{%0,%1,%2,%3},{%4,%5,%6,%7},{%8,%9},{%0,%1,%2,%3};"
                 : "+f"(c0), "+f"(c1), "+f"(c2), "+f"(c3)
                 : "r"(a0), "r"(a1), "r"(a2), "r"(a3), "r"(b0), "r"(b1));
}

// fast exp2, FMA-only (no MUFU). Valid for |x| < ~100.
__device__ __forceinline__ float exp2_fast(float x) {
    x = fmaxf(x, -120.0f);
    float r  = x + 12582912.0f;
    float f  = x - (r - 12582912.0f);
    int   n  = __float_as_int(r) - 0x4B400000;
    float sc = __int_as_float((n + 127) << 23);
    float p  = 0.00133336f;
    p = fmaf(p, f, 0.00961813f);
    p = fmaf(p, f, 0.05550411f);
    p = fmaf(p, f, 0.24022651f);
    p = fmaf(p, f, 0.69314718f);
    p = fmaf(p, f, 1.0f);
    return p * sc;
}

// fragment-packed layout, pitch 64, XOR swizzle:
// within each 16-col block: position = 4*(c&3) + ((c>>2)&3)  -> one 16B chunk
// holds k = {t, t+4, t+8, t+12}; chunk index ^= (row&7) for bank spread.
__device__ __forceinline__ int fpidx(int row, int col) {
    int blk = col >> 4, w = col & 15;
    int pc  = (blk << 4) | ((w & 3) << 2) | (w >> 2);
    int ch  = (pc >> 2) ^ (row & 7);
    return (row << 6) + (ch << 2) + (pc & 3);
}

// ---------------- tf32 GEMM core: C = A[M,K] @ W[N,K]^T + bias -------------
// CTA 128x128, BK=16, 256 thr = 8 warps (2x4), warp tile 64x32, pitch 20.
#define GP 20
__device__ __forceinline__
void gemm_core(const float* __restrict__ A, const float* __restrict__ W,
               const float* __restrict__ bias, float* __restrict__ C,
               int M, int N, int K)
{
    __shared__ float As[128 * GP];
    __shared__ float Bs[128 * GP];

    const int tid  = threadIdx.x;
    const int lane = tid & 31, wid = tid >> 5;
    const int g = lane >> 2, t = lane & 3;
    const int wm = wid >> 2;
    const int wn = wid & 3;
    const int bm = blockIdx.y << 7, bn = blockIdx.x << 7;

    const int r0 = tid >> 2, k40 = (tid & 3) << 2;
    const int r1 = r0 + 64;

    const float* Ab = A + (size_t)bm * K;
    const float* Wb = W + (size_t)bn * K;

    float4 pa0 = *(const float4*)(Ab + (size_t)r0 * K + k40);
    float4 pa1 = *(const float4*)(Ab + (size_t)r1 * K + k40);
    float4 pb0 = *(const float4*)(Wb + (size_t)r0 * K + k40);
    float4 pb1 = *(const float4*)(Wb + (size_t)r1 * K + k40);

    float acc[4][4][4];
#pragma unroll
    for (int mi = 0; mi < 4; mi++)
#pragma unroll
        for (int ni = 0; ni < 4; ni++)
#pragma unroll
            for (int c = 0; c < 4; c++) acc[mi][ni][c] = 0.0f;

    for (int kt = 0; kt < K; kt += 16) {
        __syncthreads();
        {
            float4 q;
            q.x = tf2f(pa0.x); q.y = tf2f(pa0.y); q.z = tf2f(pa0.z); q.w = tf2f(pa0.w);
            *(float4*)&As[r0 * GP + k40] = q;
            q.x = tf2f(pa1.x); q.y = tf2f(pa1.y); q.z = tf2f(pa1.z); q.w = tf2f(pa1.w);
            *(float4*)&As[r1 * GP + k40] = q;
            q.x = tf2f(pb0.x); q.y = tf2f(pb0.y); q.z = tf2f(pb0.z); q.w = tf2f(pb0.w);
            *(float4*)&Bs[r0 * GP + k40] = q;
            q.x = tf2f(pb1.x); q.y = tf2f(pb1.y); q.z = tf2f(pb1.z); q.w = tf2f(pb1.w);
            *(float4*)&Bs[r1 * GP + k40] = q;
        }
        __syncthreads();

        if (kt + 16 < K) {
            pa0 = *(const float4*)(Ab + (size_t)r0 * K + (kt + 16) + k40);
            pa1 = *(const float4*)(Ab + (size_t)r1 * K + (kt + 16) + k40);
            pb0 = *(const float4*)(Wb + (size_t)r0 * K + (kt + 16) + k40);
            pb1 = *(const float4*)(Wb + (size_t)r1 * K + (kt + 16) + k40);
        }

#pragma unroll
        for (int k8 = 0; k8 < 16; k8 += 8) {
            uint32_t af[4][4], bf[4][2];
#pragma unroll
            for (int mi = 0; mi < 4; mi++) {
                int base = ((wm << 6) + (mi << 4) + g) * GP + k8 + t;
                af[mi][0] = __float_as_uint(As[base]);
                af[mi][1] = __float_as_uint(As[base + 8 * GP]);
                af[mi][2] = __float_as_uint(As[base + 4]);
                af[mi][3] = __float_as_uint(As[base + 8 * GP + 4]);
            }
#pragma unroll
            for (int ni = 0; ni < 4; ni++) {
                int bb = ((wn << 5) + (ni << 3) + g) * GP + k8 + t;
                bf[ni][0] = __float_as_uint(Bs[bb]);
                bf[ni][1] = __float_as_uint(Bs[bb + 4]);
            }
#pragma unroll
            for (int mi = 0; mi < 4; mi++)
#pragma unroll
                for (int ni = 0; ni < 4; ni++)
                    mma8(acc[mi][ni][0], acc[mi][ni][1], acc[mi][ni][2], acc[mi][ni][3],
                         af[mi][0], af[mi][1], af[mi][2], af[mi][3],
                         bf[ni][0], bf[ni][1]);
        }
    }

#pragma unroll
    for (int ni = 0; ni < 4; ni++) {
        int col = bn + (wn << 5) + (ni << 3) + (t << 1);
        float2 bv = *(const float2*)&bias[col];
#pragma unroll
        for (int mi = 0; mi < 4; mi++) {
            int row = bm + (wm << 6) + (mi << 4) + g;
            float2 o0, o1;
            o0.x = acc[mi][ni][0] + bv.x; o0.y = acc[mi][ni][1] + bv.y;
            o1.x = acc[mi][ni][2] + bv.x; o1.y = acc[mi][ni][3] + bv.y;
            *(float2*)&C[(size_t)row * N + col]       = o0;
            *(float2*)&C[(size_t)(row + 8) * N + col] = o1;
        }
    }
}

__global__ __launch_bounds__(256)
void gemm_qkv(const float* __restrict__ x,
              const float* __restrict__ Wq, const float* __restrict__ bq,
              const float* __restrict__ Wk, const float* __restrict__ bk,
              const float* __restrict__ Wv, const float* __restrict__ bv,
              float* __restrict__ Qp, float* __restrict__ Kp, float* __restrict__ Vp)
{
    const float* W; const float* b; float* C;
    if (blockIdx.z == 0)      { W = Wq; b = bq; C = Qp; }
    else if (blockIdx.z == 1) { W = Wk; b = bk; C = Kp; }
    else                      { W = Wv; b = bv; C = Vp; }
    gemm_core(x, W, b, C, MROWS, EMBED, EMBED);
}

__global__ __launch_bounds__(256)
void gemm_one(const float* __restrict__ A, const float* __restrict__ W,
              const float* __restrict__ bias, float* __restrict__ C)
{
    gemm_core(A, W, bias, C, MROWS, EMBED, EMBED);
}

// ---------------- flash attention, tf32 mma, 128q x 64k tiles ---------------
// 256 thr = 8 warps (4 row-groups x 2 col-groups), warp tile 32x32 both phases.
// sQ/sK/sP: fragment-packed pitch-64 layout (LDS.128 = 2 k-steps of frags).
// sV: natural pitch 72 (conflict-free scalar B-frag loads).
#define VP 72
#define SQ_OFF 0
#define SK_OFF 8192
#define SP_OFF 12288
#define SV_OFF 20480
#define SL_OFF 25088
#define FLASH_SMEM ((25344) * 4)

__global__ __launch_bounds__(256, 2)
void flash_tf32(const float* __restrict__ Q, const float* __restrict__ K,
                const float* __restrict__ V, const float* __restrict__ z,
                float* __restrict__ ctx)
{
    extern __shared__ float sm[];
    float* sQ = sm + SQ_OFF;
    float* sK = sm + SK_OFF;
    float* sP = sm + SP_OFF;
    float* sV = sm + SV_OFF;
    float* sL = sm + SL_OFF;

    const int tid  = threadIdx.x;
    const int lane = tid & 31, wid = tid >> 5;
    const int g = lane >> 2, t = lane & 3;
    const int wm = wid >> 1;              // 0..3 (32-row group)
    const int wn = wid & 1;               // 0..1 (32-col group)
    const int b = blockIdx.z, h = blockIdx.y;
    const int q0 = blockIdx.x << 7;
    const size_t base = (size_t)b * SEQ * EMBED + (size_t)h * HDIM;

    const float zg = z[h];
    const float gate = 1.0f / (1.0f + __expf(-zg));
    const float qscale = gate * 0.125f * 1.44269504f;  // gate/sqrt(64)*log2e

    const int r  = tid >> 4;              // 0..15
    const int dc = (tid & 15) << 2;       // 0..60

    // stage Q (scaled, tf32, fragment-packed)
#pragma unroll
    for (int i = 0; i < 8; i++) {
        int rr = r + (i << 4);
        float4 v = *(const float4*)&Q[base + (size_t)(q0 + rr) * EMBED + dc];
        sQ[fpidx(rr, dc + 0)] = tf2f(v.x * qscale);
        sQ[fpidx(rr, dc + 1)] = tf2f(v.y * qscale);
        sQ[fpidx(rr, dc + 2)] = tf2f(v.z * qscale);
        sQ[fpidx(rr, dc + 3)] = tf2f(v.w * qscale);
    }

    float o[2][4][4];
#pragma unroll
    for (int mi = 0; mi < 2; mi++)
#pragma unroll
        for (int ni = 0; ni < 4; ni++)
#pragma unroll
            for (int c = 0; c < 4; c++) o[mi][ni][c] = 0.0f;
    float lp[2][2] = {{0.f, 0.f}, {0.f, 0.f}};

    const int rA0 = (wm << 5) + g;        // mi=0 low row
    const int rA1 = rA0 + 16;             // mi=1 low row

    for (int n0 = 0; n0 < SEQ; n0 += 64) {
        __syncthreads();   // prior S/PV reads of sK/sP/sV done
        // stage K (packed) and V (natural)
#pragma unroll
        for (int i = 0; i < 4; i++) {
            int rr = r + (i << 4);
            float4 kk = *(const float4*)&K[base + (size_t)(n0 + rr) * EMBED + dc];
            sK[fpidx(rr, dc + 0)] = tf2f(kk.x);
            sK[fpidx(rr, dc + 1)] = tf2f(kk.y);
            sK[fpidx(rr, dc + 2)] = tf2f(kk.z);
            sK[fpidx(rr, dc + 3)] = tf2f(kk.w);
            float4 vv = *(const float4*)&V[base + (size_t)(n0 + rr) * EMBED + dc];
            float4 w;
            w.x = tf2f(vv.x); w.y = tf2f(vv.y); w.z = tf2f(vv.z); w.w = tf2f(vv.w);
            *(float4*)&sV[rr * VP + dc] = w;
        }
        __syncthreads();

        // S = Q K^T : per k16 one LDS.128 per fragment row covers 2 k-steps
        float s[2][4][4];
#pragma unroll
        for (int mi = 0; mi < 2; mi++)
#pragma unroll
            for (int ni = 0; ni < 4; ni++)
#pragma unroll
                for (int c = 0; c < 4; c++) s[mi][ni][c] = 0.0f;

#pragma unroll
        for (int k16 = 0; k16 < 4; k16++) {
            const int chx = ((((k16 << 2) + t) ^ g) << 2);
            uint4 a0L = *(const uint4*)&sQ[(rA0      << 6) + chx];
            uint4 a0H = *(const uint4*)&sQ[((rA0 + 8) << 6) + chx];
            uint4 a1L = *(const uint4*)&sQ[(rA1      << 6) + chx];
            uint4 a1H = *(const uint4*)&sQ[((rA1 + 8) << 6) + chx];
            uint4 bf[4];
#pragma unroll
            for (int ni = 0; ni < 4; ni++)
                bf[ni] = *(const uint4*)&sK[(((wn << 5) + (ni << 3) + g) << 6) + chx];
#pragma unroll
            for (int ni = 0; ni < 4; ni++) {
                mma8(s[0][ni][0], s[0][ni][1], s[0][ni][2], s[0][ni][3],
                     a0L.x, a0H.x, a0L.y, a0H.y, bf[ni].x, bf[ni].y);
                mma8(s[1][ni][0], s[1][ni][1], s[1][ni][2], s[1][ni][3],
                     a1L.x, a1H.x, a1L.y, a1H.y, bf[ni].x, bf[ni].y);
                mma8(s[0][ni][0], s[0][ni][1], s[0][ni][2], s[0][ni][3],
                     a0L.z, a0H.z, a0L.w, a0H.w, bf[ni].z, bf[ni].w);
                mma8(s[1][ni][0], s[1][ni][1], s[1][ni][2], s[1][ni][3],
                     a1L.z, a1H.z, a1L.w, a1H.w, bf[ni].z, bf[ni].w);
            }
        }

        // exp (base-2, scale in Q) + partial row sums + packed P store
#pragma unroll
        for (int mi = 0; mi < 2; mi++) {
            int rowL = (wm << 5) + (mi << 4) + g;
#pragma unroll
            for (int ni = 0; ni < 4; ni++) {
                float p0 = exp2_fast(s[mi][ni][0]);
                float p1 = exp2_fast(s[mi][ni][1]);
                float p2 = exp2_fast(s[mi][ni][2]);
                float p3 = exp2_fast(s[mi][ni][3]);
                lp[mi][0] += p0 + p1;
                lp[mi][1] += p2 + p3;
                int C = (wn << 5) + (ni << 3) + (t << 1);
                sP[fpidx(rowL,     C)]     = __uint_as_float(f2tf(p0));
                sP[fpidx(rowL,     C + 1)] = __uint_as_float(f2tf(p1));
                sP[fpidx(rowL + 8, C)]     = __uint_as_float(f2tf(p2));
                sP[fpidx(rowL + 8, C + 1)] = __uint_as_float(f2tf(p3));
            }
        }
        __syncthreads();   // full P visible; S-phase sK reads done

        // O += P V  (A from packed sP, B scalar from natural sV)
#pragma unroll
        for (int k16 = 0; k16 < 4; k16++) {
            const int chx = ((((k16 << 2) + t) ^ g) << 2);
            uint4 p0L = *(const uint4*)&sP[(rA0      << 6) + chx];
            uint4 p0H = *(const uint4*)&sP[((rA0 + 8) << 6) + chx];
            uint4 p1L = *(const uint4*)&sP[(rA1      << 6) + chx];
            uint4 p1H = *(const uint4*)&sP[((rA1 + 8) << 6) + chx];
            const int nb = (k16 << 4);
#pragma unroll
            for (int ni = 0; ni < 4; ni++) {
                int dcol = (wn << 5) + (ni << 3) + g;
                uint32_t b0 = __float_as_uint(sV[(nb + t) * VP + dcol]);
                uint32_t b1 = __float_as_uint(sV[(nb + t + 4) * VP + dcol]);
                mma8(o[0][ni][0], o[0][ni][1], o[0][ni][2], o[0][ni][3],
                     p0L.x, p0H.x, p0L.y, p0H.y, b0, b1);
                mma8(o[1][ni][0], o[1][ni][1], o[1][ni][2], o[1][ni][3],
                     p1L.x, p1H.x, p1L.y, p1H.y, b0, b1);
                uint32_t c0 = __float_as_uint(sV[(nb + 8 + t) * VP + dcol]);
                uint32_t c1 = __float_as_uint(sV[(nb + 12 + t) * VP + dcol]);
                mma8(o[0][ni][0], o[0][ni][1], o[0][ni][2], o[0][ni][3],
                     p0L.z, p0H.z, p0L.w, p0H.w, c0, c1);
                mma8(o[1][ni][0], o[1][ni][1], o[1][ni][2], o[1][ni][3],
                     p1L.z, p1H.z, p1L.w, p1H.w, c0, c1);
            }
        }
    }

    // final row-sum reduction: over t lanes (shfl), then over wn warps (smem)
#pragma unroll
    for (int mi = 0; mi < 2; mi++) {
        float v0 = lp[mi][0], v1 = lp[mi][1];
        v0 += __shfl_xor_sync(0xffffffffu, v0, 1);
        v0 += __shfl_xor_sync(0xffffffffu, v0, 2);
        v1 += __shfl_xor_sync(0xffffffffu, v1, 1);
        v1 += __shfl_xor_sync(0xffffffffu, v1, 2);
        if (t == 0) {
            int rowL = (wm << 5) + (mi << 4) + g;
            sL[(rowL << 1) + wn]       = v0;
            sL[((rowL + 8) << 1) + wn] = v1;
        }
    }
    __syncthreads();

#pragma unroll
    for (int mi = 0; mi < 2; mi++) {
        int rowL = (wm << 5) + (mi << 4) + g;
        float inv0 = 1.0f / (sL[rowL << 1] + sL[(rowL << 1) + 1]);
        float inv1 = 1.0f / (sL[(rowL + 8) << 1] + sL[((rowL + 8) << 1) + 1]);
#pragma unroll
        for (int ni = 0; ni < 4; ni++) {
            int C = (wn << 5) + (ni << 3) + (t << 1);
            float2 o0, o1;
            o0.x = o[mi][ni][0] * inv0; o0.y = o[mi][ni][1] * inv0;
            o1.x = o[mi][ni][2] * inv1; o1.y = o[mi][ni][3] * inv1;
            *(float2*)&ctx[base + (size_t)(q0 + rowL) * EMBED + C]     = o0;
            *(float2*)&ctx[base + (size_t)(q0 + rowL + 8) * EMBED + C] = o1;
        }
    }
}

// ---------------- penalty scalar -------------------------------------------
__global__ void penalty_kernel(const float* __restrict__ z, float* __restrict__ out)
{
    int l = threadIdx.x;
    float v = 0.0f;
    if (l < HEADS) v = 1.0f / (1.0f + __expf(-z[l]));
    v += __shfl_xor_sync(0xffffffffu, v, 1);
    v += __shfl_xor_sync(0xffffffffu, v, 2);
    v += __shfl_xor_sync(0xffffffffu, v, 4);
    v += __shfl_xor_sync(0xffffffffu, v, 8);
    if (l == 0) out[0] = v * 0.01f;
}

// ---------------- launch ----------------------------------------------------
extern "C" void kernel_launch(void* const* d_in, const int* in_sizes, int n_in,
                              void* d_out, int out_size)
{
    const float* x  = (const float*)d_in[0];
    const float* Wq = (const float*)d_in[1];
    const float* bq = (const float*)d_in[2];
    const float* Wk = (const float*)d_in[3];
    const float* bk = (const float*)d_in[4];
    const float* Wv = (const float*)d_in[5];
    const float* bv = (const float*)d_in[6];
    const float* Wo = (const float*)d_in[7];
    const float* bo = (const float*)d_in[8];
    const float* z  = (const float*)d_in[9];
    float* out = (float*)d_out;

    float *Qp, *Kp, *Vp, *Cp;
    cudaGetSymbolAddress((void**)&Qp, g_Q);
    cudaGetSymbolAddress((void**)&Kp, g_K);
    cudaGetSymbolAddress((void**)&Vp, g_V);
    cudaGetSymbolAddress((void**)&Cp, g_C);

    gemm_qkv<<<dim3(EMBED / 128, MROWS / 128, 3), 256>>>(
        x, Wq, bq, Wk, bk, Wv, bv, Qp, Kp, Vp);

    cudaFuncSetAttribute(flash_tf32, cudaFuncAttributeMaxDynamicSharedMemorySize,
                         FLASH_SMEM);
    flash_tf32<<<dim3(SEQ / 128, HEADS, BATCH), 256, FLASH_SMEM>>>(Qp, Kp, Vp, z, Cp);

    gemm_one<<<dim3(EMBED / 128, MROWS / 128), 256>>>(Cp, Wo, bo, out);

    if (out_size > OUT_ELEMS)
        penalty_kernel<<<1, 32>>>(z, out + OUT_ELEMS);
}

// round 10
// speedup vs baseline: 1.1405x; 1.1405x over previous
#include <cuda_runtime.h>
#include <cstdint>

#define EMBED   1024
#define HEADS   16
#define HDIM    64
#define BATCH   2
#define SEQ     2048
#define MROWS   (BATCH*SEQ)          // 4096
#define OUT_ELEMS (MROWS*EMBED)      // 4194304

// ---------------- scratch (device globals: no allocation allowed) ----------
__device__ float g_Q[MROWS*EMBED];
__device__ float g_K[MROWS*EMBED];
__device__ float g_V[MROWS*EMBED];
__device__ float g_C[MROWS*EMBED];

// ---------------- helpers ---------------------------------------------------
__device__ __forceinline__ uint32_t f2tf(float f) {
    uint32_t u; asm("cvt.rna.tf32.f32 %0, %1;" : "=r"(u) : "f"(f)); return u;
}
__device__ __forceinline__ float tf2f(float f) { return __uint_as_float(f2tf(f)); }

__device__ __forceinline__ void mma8(float& c0, float& c1, float& c2, float& c3,
                                     uint32_t a0, uint32_t a1, uint32_t a2, uint32_t a3,
                                     uint32_t b0, uint32_t b1)
{
    asm volatile("mma.sync.aligned.m16n8k8.row.col.f32.tf32.tf32.f32 "
                 "{%0,%1,%2,%3},{%4,%5,%6,%7},{%8,%9},{%0,%1,%2,%3};"
                 : "+f"(c0), "+f"(c1), "+f"(c2), "+f"(c3)
                 : "r"(a0), "r"(a1), "r"(a2), "r"(a3), "r"(b0), "r"(b1));
}

// fast exp2, FMA-only (no MUFU).
__device__ __forceinline__ float exp2_fast(float x) {
    x = fmaxf(x, -120.0f);
    float r  = x + 12582912.0f;
    float f  = x - (r - 12582912.0f);
    int   n  = __float_as_int(r) - 0x4B400000;
    float sc = __int_as_float((n + 127) << 23);
    float p  = 0.00133336f;
    p = fmaf(p, f, 0.00961813f);
    p = fmaf(p, f, 0.05550411f);
    p = fmaf(p, f, 0.24022651f);
    p = fmaf(p, f, 0.69314718f);
    p = fmaf(p, f, 1.0f);
    return p * sc;
}

// packed k-fragment layout, pitch 64 floats.
// 16B chunk w of 16-col block holds cols {t, t+4, t+8, t+12}; swizzle flips
// chunk bit2 on odd rows -> per-phase conflict-free fragment loads.
__device__ __forceinline__ int fp2(int r, int c) {
    int chunk = ((((c >> 4) << 2) | (c & 3)) ^ ((r & 1) << 2));
    return (r << 6) + (chunk << 2) + ((c >> 2) & 3);
}

// ---------------- tf32 GEMM core: C = A[M,K] @ W[N,K]^T + bias -------------
// CTA 128x128, BK=16, 256 thr = 8 warps (2x4), warp tile 64x32, pitch 20.
// Double-buffered smem: ONE barrier per K-stage, LDG hidden under compute.
#define GP 20
__device__ __forceinline__
void gemm_core(const float* __restrict__ A, const float* __restrict__ W,
               const float* __restrict__ bias, float* __restrict__ C,
               int M, int N, int K)
{
    __shared__ float As[2][128 * GP];
    __shared__ float Bs[2][128 * GP];

    const int tid  = threadIdx.x;
    const int lane = tid & 31, wid = tid >> 5;
    const int g = lane >> 2, t = lane & 3;
    const int wm = wid >> 2;
    const int wn = wid & 3;
    const int bm = blockIdx.y << 7, bn = blockIdx.x << 7;

    const int r0 = tid >> 2, k40 = (tid & 3) << 2;
    const int r1 = r0 + 64;

    const float* Ab = A + (size_t)bm * K;
    const float* Wb = W + (size_t)bn * K;

    float4 pa0 = *(const float4*)(Ab + (size_t)r0 * K + k40);
    float4 pa1 = *(const float4*)(Ab + (size_t)r1 * K + k40);
    float4 pb0 = *(const float4*)(Wb + (size_t)r0 * K + k40);
    float4 pb1 = *(const float4*)(Wb + (size_t)r1 * K + k40);

    float acc[4][4][4];
#pragma unroll
    for (int mi = 0; mi < 4; mi++)
#pragma unroll
        for (int ni = 0; ni < 4; ni++)
#pragma unroll
            for (int c = 0; c < 4; c++) acc[mi][ni][c] = 0.0f;

    // stage 0
    {
        float4 q;
        q.x = tf2f(pa0.x); q.y = tf2f(pa0.y); q.z = tf2f(pa0.z); q.w = tf2f(pa0.w);
        *(float4*)&As[0][r0 * GP + k40] = q;
        q.x = tf2f(pa1.x); q.y = tf2f(pa1.y); q.z = tf2f(pa1.z); q.w = tf2f(pa1.w);
        *(float4*)&As[0][r1 * GP + k40] = q;
        q.x = tf2f(pb0.x); q.y = tf2f(pb0.y); q.z = tf2f(pb0.z); q.w = tf2f(pb0.w);
        *(float4*)&Bs[0][r0 * GP + k40] = q;
        q.x = tf2f(pb1.x); q.y = tf2f(pb1.y); q.z = tf2f(pb1.z); q.w = tf2f(pb1.w);
        *(float4*)&Bs[0][r1 * GP + k40] = q;
    }
    __syncthreads();

    const int NS = K >> 4;
    for (int s = 0; s < NS; s++) {
        const int cur = s & 1;
        const bool more = (s + 1 < NS);
        if (more) {
            const int kt = (s + 1) << 4;
            pa0 = *(const float4*)(Ab + (size_t)r0 * K + kt + k40);
            pa1 = *(const float4*)(Ab + (size_t)r1 * K + kt + k40);
            pb0 = *(const float4*)(Wb + (size_t)r0 * K + kt + k40);
            pb1 = *(const float4*)(Wb + (size_t)r1 * K + kt + k40);
        }

        const float* Ac = As[cur];
        const float* Bc = Bs[cur];
#pragma unroll
        for (int k8 = 0; k8 < 16; k8 += 8) {
            uint32_t af[4][4], bf[4][2];
#pragma unroll
            for (int mi = 0; mi < 4; mi++) {
                int base = ((wm << 6) + (mi << 4) + g) * GP + k8 + t;
                af[mi][0] = __float_as_uint(Ac[base]);
                af[mi][1] = __float_as_uint(Ac[base + 8 * GP]);
                af[mi][2] = __float_as_uint(Ac[base + 4]);
                af[mi][3] = __float_as_uint(Ac[base + 8 * GP + 4]);
            }
#pragma unroll
            for (int ni = 0; ni < 4; ni++) {
                int bb = ((wn << 5) + (ni << 3) + g) * GP + k8 + t;
                bf[ni][0] = __float_as_uint(Bc[bb]);
                bf[ni][1] = __float_as_uint(Bc[bb + 4]);
            }
#pragma unroll
            for (int mi = 0; mi < 4; mi++)
#pragma unroll
                for (int ni = 0; ni < 4; ni++)
                    mma8(acc[mi][ni][0], acc[mi][ni][1], acc[mi][ni][2], acc[mi][ni][3],
                         af[mi][0], af[mi][1], af[mi][2], af[mi][3],
                         bf[ni][0], bf[ni][1]);
        }

        if (more) {
            const int nxt = cur ^ 1;
            float4 q;
            q.x = tf2f(pa0.x); q.y = tf2f(pa0.y); q.z = tf2f(pa0.z); q.w = tf2f(pa0.w);
            *(float4*)&As[nxt][r0 * GP + k40] = q;
            q.x = tf2f(pa1.x); q.y = tf2f(pa1.y); q.z = tf2f(pa1.z); q.w = tf2f(pa1.w);
            *(float4*)&As[nxt][r1 * GP + k40] = q;
            q.x = tf2f(pb0.x); q.y = tf2f(pb0.y); q.z = tf2f(pb0.z); q.w = tf2f(pb0.w);
            *(float4*)&Bs[nxt][r0 * GP + k40] = q;
            q.x = tf2f(pb1.x); q.y = tf2f(pb1.y); q.z = tf2f(pb1.z); q.w = tf2f(pb1.w);
            *(float4*)&Bs[nxt][r1 * GP + k40] = q;
            __syncthreads();
        }
    }

#pragma unroll
    for (int ni = 0; ni < 4; ni++) {
        int col = bn + (wn << 5) + (ni << 3) + (t << 1);
        float2 bv = *(const float2*)&bias[col];
#pragma unroll
        for (int mi = 0; mi < 4; mi++) {
            int row = bm + (wm << 6) + (mi << 4) + g;
            float2 o0, o1;
            o0.x = acc[mi][ni][0] + bv.x; o0.y = acc[mi][ni][1] + bv.y;
            o1.x = acc[mi][ni][2] + bv.x; o1.y = acc[mi][ni][3] + bv.y;
            *(float2*)&C[(size_t)row * N + col]       = o0;
            *(float2*)&C[(size_t)(row + 8) * N + col] = o1;
        }
    }
}

__global__ __launch_bounds__(256)
void gemm_qkv(const float* __restrict__ x,
              const float* __restrict__ Wq, const float* __restrict__ bq,
              const float* __restrict__ Wk, const float* __restrict__ bk,
              const float* __restrict__ Wv, const float* __restrict__ bv,
              float* __restrict__ Qp, float* __restrict__ Kp, float* __restrict__ Vp)
{
    const float* W; const float* b; float* C;
    if (blockIdx.z == 0)      { W = Wq; b = bq; C = Qp; }
    else if (blockIdx.z == 1) { W = Wk; b = bk; C = Kp; }
    else                      { W = Wv; b = bv; C = Vp; }
    gemm_core(x, W, b, C, MROWS, EMBED, EMBED);
}

__global__ __launch_bounds__(256)
void gemm_one(const float* __restrict__ A, const float* __restrict__ W,
              const float* __restrict__ bias, float* __restrict__ C)
{
    gemm_core(A, W, bias, C, MROWS, EMBED, EMBED);
}

// ---------------- flash attention: warp-owns-rows design --------------------
// CTA: 128q x 64k tile, 8 warps, warp = 16 rows x ALL 64 cols (ni=8).
// Q A-frags: loaded ONCE into 32 regs. K: packed layout (corrected swizzle).
// V: natural pitch 72. P: warp-private (reuses sQ region), column-shift +4g.
#define VP 72
#define SK_F 8192                     // sK float offset (sQ/sP = [0,8192))
#define SV_F (8192 + 4096)            // sV float offset
#define FLASH_SMEM ((8192 + 4096 + 64*VP) * 4)   // 67584 B

__global__ __launch_bounds__(256)
void flash_tf32(const float* __restrict__ Q, const float* __restrict__ K,
                const float* __restrict__ V, const float* __restrict__ z,
                float* __restrict__ ctx)
{
    extern __shared__ float sm[];
    float* sQP = sm;                  // Q staging, then per-warp P
    float* sK  = sm + SK_F;
    float* sV  = sm + SV_F;

    const int tid  = threadIdx.x;
    const int lane = tid & 31, wid = tid >> 5;
    const int g = lane >> 2, t = lane & 3;
    const int b = blockIdx.z, h = blockIdx.y;
    const int q0 = blockIdx.x << 7;
    const size_t base = (size_t)b * SEQ * EMBED + (size_t)h * HDIM;

    const float zg = z[h];
    const float gate = 1.0f / (1.0f + __expf(-zg));
    const float qscale = gate * 0.125f * 1.44269504f;  // gate/sqrt(64)*log2e

    const int r  = tid >> 4;              // 0..15
    const int dc = (tid & 15) << 2;       // 0..60

    // ---- stage Q packed (scaled tf32), extract A-frags to regs, free sQ ----
#pragma unroll
    for (int i = 0; i < 8; i++) {
        int rr = r + (i << 4);            // 0..127
        float4 v = *(const float4*)&Q[base + (size_t)(q0 + rr) * EMBED + dc];
        sQP[fp2(rr, dc + 0)] = tf2f(v.x * qscale);
        sQP[fp2(rr, dc + 1)] = tf2f(v.y * qscale);
        sQP[fp2(rr, dc + 2)] = tf2f(v.z * qscale);
        sQP[fp2(rr, dc + 3)] = tf2f(v.w * qscale);
    }
    __syncthreads();

    uint32_t qf[8][4];
    {
        const int rq0 = (wid << 4) + g;   // warp's low frag row
        const int rq1 = rq0 + 8;
#pragma unroll
        for (int k16 = 0; k16 < 4; k16++) {
            int ch = (((k16 << 2) | t) ^ ((g & 1) << 2)) << 2;
            uint4 aL = *(const uint4*)&sQP[(rq0 << 6) + ch];
            uint4 aH = *(const uint4*)&sQP[(rq1 << 6) + ch];
            int kb = k16 << 1;
            qf[kb][0]     = aL.x; qf[kb][1]     = aH.x;
            qf[kb][2]     = aL.y; qf[kb][3]     = aH.y;
            qf[kb + 1][0] = aL.z; qf[kb + 1][1] = aH.z;
            qf[kb + 1][2] = aL.w; qf[kb + 1][3] = aH.w;
        }
    }
    __syncthreads();                      // sQP now reusable as P

    float* sPw = sQP + (wid << 10);       // warp-private 16x64 P

    float o[8][4];
#pragma unroll
    for (int ni = 0; ni < 8; ni++)
#pragma unroll
        for (int c = 0; c < 4; c++) o[ni][c] = 0.0f;
    float lp0 = 0.0f, lp1 = 0.0f;
    const int g4 = g << 2;

    for (int n0 = 0; n0 < SEQ; n0 += 64) {
        __syncthreads();                  // prev S (sK) and PV (sV) done
        // stage K packed + V natural
#pragma unroll
        for (int i = 0; i < 4; i++) {
            int rr = r + (i << 4);        // 0..63
            float4 kk = *(const float4*)&K[base + (size_t)(n0 + rr) * EMBED + dc];
            sK[fp2(rr, dc + 0)] = tf2f(kk.x);
            sK[fp2(rr, dc + 1)] = tf2f(kk.y);
            sK[fp2(rr, dc + 2)] = tf2f(kk.z);
            sK[fp2(rr, dc + 3)] = tf2f(kk.w);
            float4 vv = *(const float4*)&V[base + (size_t)(n0 + rr) * EMBED + dc];
            float4 w;
            w.x = tf2f(vv.x); w.y = tf2f(vv.y); w.z = tf2f(vv.z); w.w = tf2f(vv.w);
            *(float4*)&sV[rr * VP + dc] = w;
        }
        __syncthreads();

        // S = Q K^T per ni-pair, then softmax + P store (register economy)
#pragma unroll
        for (int np = 0; np < 4; np++) {
            float s0[4] = {0.f, 0.f, 0.f, 0.f};
            float s1[4] = {0.f, 0.f, 0.f, 0.f};
            const int row0 = (np << 4) + g;
            const int row1 = row0 + 8;
#pragma unroll
            for (int k16 = 0; k16 < 4; k16++) {
                int ch = (((k16 << 2) | t) ^ ((g & 1) << 2)) << 2;
                uint4 b0v = *(const uint4*)&sK[(row0 << 6) + ch];
                uint4 b1v = *(const uint4*)&sK[(row1 << 6) + ch];
                int kb = k16 << 1;
                mma8(s0[0], s0[1], s0[2], s0[3],
                     qf[kb][0], qf[kb][1], qf[kb][2], qf[kb][3], b0v.x, b0v.y);
                mma8(s0[0], s0[1], s0[2], s0[3],
                     qf[kb+1][0], qf[kb+1][1], qf[kb+1][2], qf[kb+1][3], b0v.z, b0v.w);
                mma8(s1[0], s1[1], s1[2], s1[3],
                     qf[kb][0], qf[kb][1], qf[kb][2], qf[kb][3], b1v.x, b1v.y);
                mma8(s1[0], s1[1], s1[2], s1[3],
                     qf[kb+1][0], qf[kb+1][1], qf[kb+1][2], qf[kb+1][3], b1v.z, b1v.w);
            }
            // exp + partial sums + P store (cols of ni block 2np: from s0; 2np+1: s1)
            {
                float p0 = exp2_fast(s0[0]), p1 = exp2_fast(s0[1]);
                float p2 = exp2_fast(s0[2]), p3 = exp2_fast(s0[3]);
                lp0 += p0 + p1; lp1 += p2 + p3;
                int cs = ((np << 4) + (t << 1) + g4) & 63;
                uint2 u; u.x = f2tf(p0); u.y = f2tf(p1);
                *(uint2*)&sPw[(g << 6) + cs] = u;
                u.x = f2tf(p2); u.y = f2tf(p3);
                *(uint2*)&sPw[((g + 8) << 6) + cs] = u;
            }
            {
                float p0 = exp2_fast(s1[0]), p1 = exp2_fast(s1[1]);
                float p2 = exp2_fast(s1[2]), p3 = exp2_fast(s1[3]);
                lp0 += p0 + p1; lp1 += p2 + p3;
                int cs = ((np << 4) + 8 + (t << 1) + g4) & 63;
                uint2 u; u.x = f2tf(p0); u.y = f2tf(p1);
                *(uint2*)&sPw[(g << 6) + cs] = u;
                u.x = f2tf(p2); u.y = f2tf(p3);
                *(uint2*)&sPw[((g + 8) << 6) + cs] = u;
            }
        }
        __syncwarp();                     // P visible within warp

        // O += P V  (A from warp-private P, B scalar from natural V)
#pragma unroll
        for (int kb = 0; kb < 8; kb++) {
            int c0 = ((kb << 3) + t + g4) & 63;
            int c1 = ((kb << 3) + t + 4 + g4) & 63;
            uint32_t a0 = __float_as_uint(sPw[(g << 6) + c0]);
            uint32_t a1 = __float_as_uint(sPw[((g + 8) << 6) + c0]);
            uint32_t a2 = __float_as_uint(sPw[(g << 6) + c1]);
            uint32_t a3 = __float_as_uint(sPw[((g + 8) << 6) + c1]);
            const float* vb  = &sV[((kb << 3) + t) * VP + g];
            const float* vb4 = &sV[((kb << 3) + t + 4) * VP + g];
#pragma unroll
            for (int ni = 0; ni < 8; ni++) {
                uint32_t b0 = __float_as_uint(vb[ni << 3]);
                uint32_t b1 = __float_as_uint(vb4[ni << 3]);
                mma8(o[ni][0], o[ni][1], o[ni][2], o[ni][3], a0, a1, a2, a3, b0, b1);
            }
        }
    }

    // row sums live entirely in the t-quads of this warp
    lp0 += __shfl_xor_sync(0xffffffffu, lp0, 1);
    lp0 += __shfl_xor_sync(0xffffffffu, lp0, 2);
    lp1 += __shfl_xor_sync(0xffffffffu, lp1, 1);
    lp1 += __shfl_xor_sync(0xffffffffu, lp1, 2);
    const float inv0 = 1.0f / lp0;
    const float inv1 = 1.0f / lp1;

    const int rowL = (wid << 4) + g;
#pragma unroll
    for (int ni = 0; ni < 8; ni++) {
        int c = (ni << 3) + (t << 1);
        float2 o0, o1;
        o0.x = o[ni][0] * inv0; o0.y = o[ni][1] * inv0;
        o1.x = o[ni][2] * inv1; o1.y = o[ni][3] * inv1;
        *(float2*)&ctx[base + (size_t)(q0 + rowL) * EMBED + c]     = o0;
        *(float2*)&ctx[base + (size_t)(q0 + rowL + 8) * EMBED + c] = o1;
    }
}

// ---------------- penalty scalar -------------------------------------------
__global__ void penalty_kernel(const float* __restrict__ z, float* __restrict__ out)
{
    int l = threadIdx.x;
    float v = 0.0f;
    if (l < HEADS) v = 1.0f / (1.0f + __expf(-z[l]));
    v += __shfl_xor_sync(0xffffffffu, v, 1);
    v += __shfl_xor_sync(0xffffffffu, v, 2);
    v += __shfl_xor_sync(0xffffffffu, v, 4);
    v += __shfl_xor_sync(0xffffffffu, v, 8);
    if (l == 0) out[0] = v * 0.01f;
}

// ---------------- launch ----------------------------------------------------
extern "C" void kernel_launch(void* const* d_in, const int* in_sizes, int n_in,
                              void* d_out, int out_size)
{
    const float* x  = (const float*)d_in[0];
    const float* Wq = (const float*)d_in[1];
    const float* bq = (const float*)d_in[2];
    const float* Wk = (const float*)d_in[3];
    const float* bk = (const float*)d_in[4];
    const float* Wv = (const float*)d_in[5];
    const float* bv = (const float*)d_in[6];
    const float* Wo = (const float*)d_in[7];
    const float* bo = (const float*)d_in[8];
    const float* z  = (const float*)d_in[9];
    float* out = (float*)d_out;

    float *Qp, *Kp, *Vp, *Cp;
    cudaGetSymbolAddress((void**)&Qp, g_Q);
    cudaGetSymbolAddress((void**)&Kp, g_K);
    cudaGetSymbolAddress((void**)&Vp, g_V);
    cudaGetSymbolAddress((void**)&Cp, g_C);

    gemm_qkv<<<dim3(EMBED / 128, MROWS / 128, 3), 256>>>(
        x, Wq, bq, Wk, bk, Wv, bv, Qp, Kp, Vp);

    cudaFuncSetAttribute(flash_tf32, cudaFuncAttributeMaxDynamicSharedMemorySize,
                         FLASH_SMEM);
    flash_tf32<<<dim3(SEQ / 128, HEADS, BATCH), 256, FLASH_SMEM>>>(Qp, Kp, Vp, z, Cp);

    gemm_one<<<dim3(EMBED / 128, MROWS / 128), 256>>>(Cp, Wo, bo, out);

    if (out_size > OUT_ELEMS)
        penalty_kernel<<<1, 32>>>(z, out + OUT_ELEMS);
}